// round 16
// baseline (speedup 1.0000x reference)
#include <cuda_runtime.h>
#include <cuda_fp16.h>
#include <cstdint>

// ============================================================================
// out[65536,256] = (x[65536,512] @ W[256,512]^T) * 0.125 + 0.1*bias
// R15: single-term fp16 mma.sync + 2-CTAs/SM syncthreads pipeline.
// Fix vs R14: unit stride across j is 512 float4 (was 1024 -> rows 64..127
// never written, OOB STS clobbered the B region).
// ============================================================================

#define KD 512
#define ND 256
#define MROWS 65536
#define BM 128
#define BN 128
#define KB 32                 // k-cols per stage
#define NS 16                 // KD / KB
#define NPIPE 3
#define THREADS 256

// stage (16KB): A 8K | B 8K
#define STAGE_BYTES 16384
#define SMEM_TOTAL (NPIPE * STAGE_BYTES)     // 49152 -> 2 CTAs/SM

// ---- pre-split W fp16: [half 2][kchunk 16] tiles of 8KB, SW64 swizzled ----
__device__ __align__(1024) unsigned char g_w[2 * 16 * 8192];   // 256KB

__device__ __forceinline__ uint32_t swz64(uint32_t o) {
    return o ^ ((o >> 3) & 0x30);
}
__device__ __forceinline__ uint32_t smem_u32(const void* p) {
    uint32_t a;
    asm("{ .reg .u64 t; cvta.to.shared.u64 t, %1; cvt.u32.u64 %0, t; }"
        : "=r"(a) : "l"(p));
    return a;
}
__device__ __forceinline__ void cp16(uint32_t saddr, const void* gptr) {
    asm volatile("cp.async.cg.shared.global [%0], [%1], 16;\n"
                 :: "r"(saddr), "l"(gptr));
}
#define CP_COMMIT() asm volatile("cp.async.commit_group;\n" ::: "memory")

__device__ __forceinline__ void sts128(uint32_t a, uint32_t r0, uint32_t r1,
                                       uint32_t r2, uint32_t r3) {
    asm volatile("st.shared.v4.b32 [%0], {%1,%2,%3,%4};"
                 :: "r"(a), "r"(r0), "r"(r1), "r"(r2), "r"(r3) : "memory");
}
// pack (lo arg -> low half, hi arg -> high half) as f16x2
__device__ __forceinline__ uint32_t packf16(float lo, float hi) {
    uint32_t r;
    asm("cvt.rn.f16x2.f32 %0, %1, %2;" : "=r"(r) : "f"(hi), "f"(lo));
    return r;
}

#define LDSM4(r, addr) \
    asm volatile("ldmatrix.sync.aligned.m8n8.x4.shared.b16 {%0,%1,%2,%3}, [%4];" \
                 : "=r"((r)[0]), "=r"((r)[1]), "=r"((r)[2]), "=r"((r)[3])  \
                 : "r"(addr))

#define MMA(d, a, b0, b1) \
    asm volatile("mma.sync.aligned.m16n8k16.row.col.f32.f16.f16.f32 " \
                 "{%0,%1,%2,%3}, {%4,%5,%6,%7}, {%8,%9}, {%0,%1,%2,%3};" \
                 : "+f"((d)[0]), "+f"((d)[1]), "+f"((d)[2]), "+f"((d)[3]) \
                 : "r"((a)[0]), "r"((a)[1]), "r"((a)[2]), "r"((a)[3]),    \
                   "r"(b0), "r"(b1))

// ============================================================================
// W split: fp32 -> fp16, layout g_w[half][kchunk] 8KB tiles (SW64 inside).
// ============================================================================
__global__ void split_w_kernel(const float* __restrict__ src) {
    const int n4 = ND * KD / 4;                       // 32768
    int i = blockIdx.x * blockDim.x + threadIdx.x;
    if (i >= n4) return;
    float4 v = ((const float4*)src)[i];
    int r = i >> 7;                // W row (n index) 0..255
    int c4 = i & 127;              // float4 within row
    int half = r >> 7;
    int rl = r & 127;
    int kchunk = c4 >> 3;          // 32-col chunk
    int cc = c4 & 7;
    size_t dstoff = (size_t)half * 131072 + (size_t)kchunk * 8192
                  + swz64((uint32_t)(rl * 64 + cc * 8));
    *(uint2*)(g_w + dstoff) = make_uint2(packf16(v.x, v.y), packf16(v.z, v.w));
}

// ============================================================================
// Fused GEMM: all 8 warps both produce and consume (2 CTAs/SM overlap).
// ============================================================================
// A: 128x32 fp32 = 1024 float4 = 512 units (2 consecutive float4 each).
// Thread handles units tid and tid+256: float4 base e = 2*(tid + 256*j).
__device__ __forceinline__ void load_a(float4 pf[4], const float* x, int s,
                                       int bm, int tid) {
#pragma unroll
    for (int j = 0; j < 2; j++) {
        const int e = tid * 2 + 512 * j;
        const int r = e >> 3;            // row 0..127
        const int c4 = e & 7;            // float4 col (0,2,4,6)
        const float* src = x + (size_t)(bm + r) * KD + s * KB + c4 * 4;
        pf[2 * j + 0] = *(const float4*)(src);
        pf[2 * j + 1] = *(const float4*)(src + 4);
    }
}

// cvt + STS: same mapping — one 16B fp16 chunk per unit
__device__ __forceinline__ void cvt_sts_a(uint32_t bufA, const float4 pf[4],
                                          int tid) {
#pragma unroll
    for (int j = 0; j < 2; j++) {
        const int e = tid * 2 + 512 * j;
        const int r = e >> 3;
        const int c4 = e & 7;
        const uint32_t daddr = swz64((uint32_t)(r * 64 + c4 * 8));
        float4 v0 = pf[2 * j + 0];
        float4 v1 = pf[2 * j + 1];
        sts128(bufA + daddr, packf16(v0.x, v0.y), packf16(v0.z, v0.w),
               packf16(v1.x, v1.y), packf16(v1.z, v1.w));
    }
}

__global__ void __launch_bounds__(THREADS, 2)
gemm_fused_kernel(const float* __restrict__ x, const float* __restrict__ bias,
                  float* __restrict__ out) {
    extern __shared__ __align__(1024) char smem[];
    const uint32_t sb = smem_u32(smem);
    const int tid = threadIdx.x;
    const int wid = tid >> 5;
    const int lane = tid & 31;
    const int wm = wid >> 2;       // 0..1, warp rows wm*64
    const int wn = wid & 3;        // 0..3, warp cols wn*32
    const int bn = blockIdx.x;     // fastest: bn pair co-resident (x L2 reuse)
    const int bm = blockIdx.y * BM;

    // ---- prologue ----
    // B stages 0,1 via cp.async (one commit group each)
#pragma unroll
    for (int t = 0; t < 2; t++) {
        const uint32_t bb = sb + (uint32_t)t * STAGE_BYTES + 8192;
        const size_t g = (size_t)bn * 131072 + (size_t)t * 8192;
#pragma unroll
        for (int j = 0; j < 2; j++) {
            const uint32_t o = (uint32_t)(tid + 256 * j) * 16;
            cp16(bb + o, g_w + g + o);
        }
        CP_COMMIT();
    }
    float4 pf[4];
    load_a(pf, x, 0, bm, tid);     // A stage 0 -> regs

    // per-lane ldmatrix constants
    const int lrow8 = ((lane >> 3) & 1) * 8 + (lane & 7);
    const int lk16 = (lane >> 4) * 16;
    uint32_t aoff[4], boff[2];
#pragma unroll
    for (int mi = 0; mi < 4; mi++)
        aoff[mi] = (uint32_t)((wm * 64 + mi * 16 + lrow8) * 64 + lk16);
#pragma unroll
    for (int g = 0; g < 2; g++)
        boff[g] = (uint32_t)((wn * 32 + g * 16 + lrow8) * 64 + lk16);

    float acc[4][4][4];
#pragma unroll
    for (int mi = 0; mi < 4; mi++)
#pragma unroll
        for (int ni = 0; ni < 4; ni++)
#pragma unroll
            for (int j = 0; j < 4; j++) acc[mi][ni][j] = 0.0f;

#pragma unroll 1
    for (int s = 0; s < NS; s++) {
        const uint32_t buf = sb + (uint32_t)(s % NPIPE) * STAGE_BYTES;

        // B(s) arrived?
        if (s == NS - 1)
            asm volatile("cp.async.wait_group 0;\n" ::: "memory");
        else
            asm volatile("cp.async.wait_group 1;\n" ::: "memory");

        // A(s): regs -> smem (buffer free: last read at stage s-3)
        cvt_sts_a(buf, pf, tid);
        __syncthreads();           // A(s)+B(s) visible; stage s-1 reads done

        // producers for future stages
        if (s + 2 < NS) {
            const uint32_t bb = sb + (uint32_t)((s + 2) % NPIPE) * STAGE_BYTES + 8192;
            const size_t g = (size_t)bn * 131072 + (size_t)(s + 2) * 8192;
#pragma unroll
            for (int j = 0; j < 2; j++) {
                const uint32_t o = (uint32_t)(tid + 256 * j) * 16;
                cp16(bb + o, g_w + g + o);
            }
            CP_COMMIT();
        }
        if (s + 1 < NS) load_a(pf, x, s + 1, bm, tid);

        // ---- consumer: LDSM + MMA ----
        const uint32_t bufA = buf;
        const uint32_t bufB = buf + 8192;
#pragma unroll
        for (int ks = 0; ks < 2; ks++) {
            const uint32_t kadd = (uint32_t)(ks * 32);
            uint32_t bht[2][4];
#pragma unroll
            for (int g = 0; g < 2; g++)
                LDSM4(bht[g], bufB + swz64(boff[g] + kadd));
#pragma unroll
            for (int mi = 0; mi < 4; mi++) {
                uint32_t ah[4];
                LDSM4(ah, bufA + swz64(aoff[mi] + kadd));
#pragma unroll
                for (int g = 0; g < 2; g++) {
                    MMA(acc[mi][2 * g],     ah, bht[g][0], bht[g][2]);
                    MMA(acc[mi][2 * g + 1], ah, bht[g][1], bht[g][3]);
                }
            }
        }
    }

    // ---- epilogue ----
    const int quad = lane >> 2;
    const int tq = lane & 3;
    const float scale = 0.125f;
#pragma unroll
    for (int mi = 0; mi < 4; mi++) {
        const int row0 = bm + wm * 64 + mi * 16 + quad;
#pragma unroll
        for (int ni = 0; ni < 4; ni++) {
            const int col = bn * BN + wn * 32 + ni * 8 + tq * 2;
            const float2 bv = *(const float2*)(bias + col);
            float2 o0, o1;
            o0.x = acc[mi][ni][0] * scale + 0.1f * bv.x;
            o0.y = acc[mi][ni][1] * scale + 0.1f * bv.y;
            o1.x = acc[mi][ni][2] * scale + 0.1f * bv.x;
            o1.y = acc[mi][ni][3] * scale + 0.1f * bv.y;
            *(float2*)(out + (size_t)row0 * ND + col) = o0;
            *(float2*)(out + (size_t)(row0 + 8) * ND + col) = o1;
        }
    }
}

// ============================================================================
extern "C" void kernel_launch(void* const* d_in, const int* in_sizes, int n_in,
                              void* d_out, int out_size) {
    const float* x      = (const float*)d_in[0];   // [65536, 512]
    const float* weight = (const float*)d_in[1];   // [256, 512]
    const float* bias   = (const float*)d_in[2];   // [256]
    float* out = (float*)d_out;                    // [65536, 256]

    cudaFuncSetAttribute(gemm_fused_kernel,
                         cudaFuncAttributeMaxDynamicSharedMemorySize, SMEM_TOTAL);

    split_w_kernel<<<128, 256>>>(weight);
    dim3 grid(ND / BN, MROWS / BM);   // (2, 512), bn fastest
    gemm_fused_kernel<<<grid, THREADS, SMEM_TOTAL>>>(x, bias, out);
}

// round 17
// speedup vs baseline: 1.0901x; 1.0901x over previous
#include <cuda_runtime.h>
#include <cuda_fp16.h>
#include <cstdint>

// ============================================================================
// out[65536,256] = (x[65536,512] @ W[256,512]^T) * 0.125 + 0.1*bias
// R16: single-term fp16 mma.sync. Same (debugged) R15 structure, but
// quarter-size CTAs: BM=64, 128 threads, 36KB smem -> 4 CTAs/SM.
// 16 warps/SM from 4 independent pipelines: sync stalls decorrelate.
// ============================================================================

#define KD 512
#define ND 256
#define MROWS 65536
#define BM 64
#define BN 128
#define KB 32                 // k-cols per stage
#define NS 16                 // KD / KB
#define NPIPE 3
#define THREADS 128

// stage (12KB): A 4K | B 8K
#define STAGE_BYTES 12288
#define A_BYTES 4096
#define SMEM_TOTAL (NPIPE * STAGE_BYTES)     // 36864 -> 4 CTAs/SM

// ---- pre-split W fp16: [half 2][kchunk 16] tiles of 8KB, SW64 swizzled ----
__device__ __align__(1024) unsigned char g_w[2 * 16 * 8192];   // 256KB

__device__ __forceinline__ uint32_t swz64(uint32_t o) {
    return o ^ ((o >> 3) & 0x30);
}
__device__ __forceinline__ uint32_t smem_u32(const void* p) {
    uint32_t a;
    asm("{ .reg .u64 t; cvta.to.shared.u64 t, %1; cvt.u32.u64 %0, t; }"
        : "=r"(a) : "l"(p));
    return a;
}
__device__ __forceinline__ void cp16(uint32_t saddr, const void* gptr) {
    asm volatile("cp.async.cg.shared.global [%0], [%1], 16;\n"
                 :: "r"(saddr), "l"(gptr));
}
#define CP_COMMIT() asm volatile("cp.async.commit_group;\n" ::: "memory")

__device__ __forceinline__ void sts128(uint32_t a, uint32_t r0, uint32_t r1,
                                       uint32_t r2, uint32_t r3) {
    asm volatile("st.shared.v4.b32 [%0], {%1,%2,%3,%4};"
                 :: "r"(a), "r"(r0), "r"(r1), "r"(r2), "r"(r3) : "memory");
}
// pack (lo arg -> low half, hi arg -> high half) as f16x2
__device__ __forceinline__ uint32_t packf16(float lo, float hi) {
    uint32_t r;
    asm("cvt.rn.f16x2.f32 %0, %1, %2;" : "=r"(r) : "f"(hi), "f"(lo));
    return r;
}

#define LDSM4(r, addr) \
    asm volatile("ldmatrix.sync.aligned.m8n8.x4.shared.b16 {%0,%1,%2,%3}, [%4];" \
                 : "=r"((r)[0]), "=r"((r)[1]), "=r"((r)[2]), "=r"((r)[3])  \
                 : "r"(addr))

#define MMA(d, a, b0, b1) \
    asm volatile("mma.sync.aligned.m16n8k16.row.col.f32.f16.f16.f32 " \
                 "{%0,%1,%2,%3}, {%4,%5,%6,%7}, {%8,%9}, {%0,%1,%2,%3};" \
                 : "+f"((d)[0]), "+f"((d)[1]), "+f"((d)[2]), "+f"((d)[3]) \
                 : "r"((a)[0]), "r"((a)[1]), "r"((a)[2]), "r"((a)[3]),    \
                   "r"(b0), "r"(b1))

// ============================================================================
// W split: fp32 -> fp16, layout g_w[half][kchunk] 8KB tiles (SW64 inside).
// ============================================================================
__global__ void split_w_kernel(const float* __restrict__ src) {
    const int n4 = ND * KD / 4;                       // 32768
    int i = blockIdx.x * blockDim.x + threadIdx.x;
    if (i >= n4) return;
    float4 v = ((const float4*)src)[i];
    int r = i >> 7;                // W row (n index) 0..255
    int c4 = i & 127;              // float4 within row
    int half = r >> 7;
    int rl = r & 127;
    int kchunk = c4 >> 3;          // 32-col chunk
    int cc = c4 & 7;
    size_t dstoff = (size_t)half * 131072 + (size_t)kchunk * 8192
                  + swz64((uint32_t)(rl * 64 + cc * 8));
    *(uint2*)(g_w + dstoff) = make_uint2(packf16(v.x, v.y), packf16(v.z, v.w));
}

// ============================================================================
// Fused GEMM: 4 small CTAs per SM, each with its own 3-stage pipeline.
// ============================================================================
// A: 64x32 fp32 = 512 float4 = 256 units (2 consecutive float4 each).
// Thread handles units tid and tid+128: float4 base e = 2*(tid + 128*j).
__device__ __forceinline__ void load_a(float4 pf[4], const float* x, int s,
                                       int bm, int tid) {
#pragma unroll
    for (int j = 0; j < 2; j++) {
        const int e = tid * 2 + 256 * j;
        const int r = e >> 3;            // row 0..63
        const int c4 = e & 7;            // float4 col (0,2,4,6)
        const float* src = x + (size_t)(bm + r) * KD + s * KB + c4 * 4;
        pf[2 * j + 0] = *(const float4*)(src);
        pf[2 * j + 1] = *(const float4*)(src + 4);
    }
}

// cvt + STS: same mapping — one 16B fp16 chunk per unit
__device__ __forceinline__ void cvt_sts_a(uint32_t bufA, const float4 pf[4],
                                          int tid) {
#pragma unroll
    for (int j = 0; j < 2; j++) {
        const int e = tid * 2 + 256 * j;
        const int r = e >> 3;
        const int c4 = e & 7;
        const uint32_t daddr = swz64((uint32_t)(r * 64 + c4 * 8));
        float4 v0 = pf[2 * j + 0];
        float4 v1 = pf[2 * j + 1];
        sts128(bufA + daddr, packf16(v0.x, v0.y), packf16(v0.z, v0.w),
               packf16(v1.x, v1.y), packf16(v1.z, v1.w));
    }
}

__global__ void __launch_bounds__(THREADS, 4)
gemm_fused_kernel(const float* __restrict__ x, const float* __restrict__ bias,
                  float* __restrict__ out) {
    extern __shared__ __align__(1024) char smem[];
    const uint32_t sb = smem_u32(smem);
    const int tid = threadIdx.x;
    const int wid = tid >> 5;
    const int lane = tid & 31;
    const int wm = wid >> 1;       // 0..1, warp rows wm*32
    const int wn = wid & 1;        // 0..1, warp cols wn*64
    const int bn = blockIdx.x;     // fastest: bn pair co-resident (x L2 reuse)
    const int bm = blockIdx.y * BM;

    // ---- prologue ----
    // B stages 0,1 via cp.async (one commit group each)
#pragma unroll
    for (int t = 0; t < 2; t++) {
        const uint32_t bb = sb + (uint32_t)t * STAGE_BYTES + A_BYTES;
        const size_t g = (size_t)bn * 131072 + (size_t)t * 8192;
#pragma unroll
        for (int j = 0; j < 4; j++) {
            const uint32_t o = (uint32_t)(tid + 128 * j) * 16;
            cp16(bb + o, g_w + g + o);
        }
        CP_COMMIT();
    }
    float4 pf[4];
    load_a(pf, x, 0, bm, tid);     // A stage 0 -> regs

    // per-lane ldmatrix constants
    const int lrow8 = ((lane >> 3) & 1) * 8 + (lane & 7);
    const int lk16 = (lane >> 4) * 16;
    uint32_t aoff[2], boff[4];
#pragma unroll
    for (int mi = 0; mi < 2; mi++)
        aoff[mi] = (uint32_t)((wm * 32 + mi * 16 + lrow8) * 64 + lk16);
#pragma unroll
    for (int g = 0; g < 4; g++)
        boff[g] = (uint32_t)((wn * 64 + g * 16 + lrow8) * 64 + lk16);

    float acc[2][8][4];
#pragma unroll
    for (int mi = 0; mi < 2; mi++)
#pragma unroll
        for (int ni = 0; ni < 8; ni++)
#pragma unroll
            for (int j = 0; j < 4; j++) acc[mi][ni][j] = 0.0f;

#pragma unroll 1
    for (int s = 0; s < NS; s++) {
        const uint32_t buf = sb + (uint32_t)(s % NPIPE) * STAGE_BYTES;

        // B(s) arrived?
        if (s == NS - 1)
            asm volatile("cp.async.wait_group 0;\n" ::: "memory");
        else
            asm volatile("cp.async.wait_group 1;\n" ::: "memory");

        // A(s): regs -> smem (buffer free: last read at stage s-3)
        cvt_sts_a(buf, pf, tid);
        __syncthreads();           // A(s)+B(s) visible; stage s-1 reads done

        // producers for future stages
        if (s + 2 < NS) {
            const uint32_t bb = sb + (uint32_t)((s + 2) % NPIPE) * STAGE_BYTES + A_BYTES;
            const size_t g = (size_t)bn * 131072 + (size_t)(s + 2) * 8192;
#pragma unroll
            for (int j = 0; j < 4; j++) {
                const uint32_t o = (uint32_t)(tid + 128 * j) * 16;
                cp16(bb + o, g_w + g + o);
            }
            CP_COMMIT();
        }
        if (s + 1 < NS) load_a(pf, x, s + 1, bm, tid);

        // ---- consumer: LDSM + MMA ----
        const uint32_t bufA = buf;
        const uint32_t bufB = buf + A_BYTES;
#pragma unroll
        for (int ks = 0; ks < 2; ks++) {
            const uint32_t kadd = (uint32_t)(ks * 32);
            uint32_t bht[4][4];
#pragma unroll
            for (int g = 0; g < 4; g++)
                LDSM4(bht[g], bufB + swz64(boff[g] + kadd));
#pragma unroll
            for (int mi = 0; mi < 2; mi++) {
                uint32_t ah[4];
                LDSM4(ah, bufA + swz64(aoff[mi] + kadd));
#pragma unroll
                for (int g = 0; g < 4; g++) {
                    MMA(acc[mi][2 * g],     ah, bht[g][0], bht[g][2]);
                    MMA(acc[mi][2 * g + 1], ah, bht[g][1], bht[g][3]);
                }
            }
        }
    }

    // ---- epilogue ----
    const int quad = lane >> 2;
    const int tq = lane & 3;
    const float scale = 0.125f;
#pragma unroll
    for (int mi = 0; mi < 2; mi++) {
        const int row0 = bm + wm * 32 + mi * 16 + quad;
#pragma unroll
        for (int ni = 0; ni < 8; ni++) {
            const int col = bn * BN + wn * 64 + ni * 8 + tq * 2;
            const float2 bv = *(const float2*)(bias + col);
            float2 o0, o1;
            o0.x = acc[mi][ni][0] * scale + 0.1f * bv.x;
            o0.y = acc[mi][ni][1] * scale + 0.1f * bv.y;
            o1.x = acc[mi][ni][2] * scale + 0.1f * bv.x;
            o1.y = acc[mi][ni][3] * scale + 0.1f * bv.y;
            *(float2*)(out + (size_t)row0 * ND + col) = o0;
            *(float2*)(out + (size_t)(row0 + 8) * ND + col) = o1;
        }
    }
}

// ============================================================================
extern "C" void kernel_launch(void* const* d_in, const int* in_sizes, int n_in,
                              void* d_out, int out_size) {
    const float* x      = (const float*)d_in[0];   // [65536, 512]
    const float* weight = (const float*)d_in[1];   // [256, 512]
    const float* bias   = (const float*)d_in[2];   // [256]
    float* out = (float*)d_out;                    // [65536, 256]

    cudaFuncSetAttribute(gemm_fused_kernel,
                         cudaFuncAttributeMaxDynamicSharedMemorySize, SMEM_TOTAL);

    split_w_kernel<<<128, 256>>>(weight);
    dim3 grid(ND / BN, MROWS / BM);   // (2, 1024), bn fastest
    gemm_fused_kernel<<<grid, THREADS, SMEM_TOTAL>>>(x, bias, out);
}